// round 7
// baseline (speedup 1.0000x reference)
#include <cuda_runtime.h>
#include <cuda_bf16.h>
#include <cstdint>

// Problem constants
#define B 16
#define S 4096
#define H 768
#define T 2000

#define TOK_PER_CTA 32
#define NCHUNK ((T + TOK_PER_CTA - 1) / TOK_PER_CTA)   // 63

// ---------------------------------------------------------------------------
// Single fused kernel. CTA = one 32-token chunk of one batch.
// Phase 1: block-reduce lens[b][0..t0) -> base; warp0 scans the chunk's lens,
//          writes packed (start | len<<16) descriptors to shared.
// Phase 2: half-token per warp-iteration: 8 warps x 8 iters cover 64 halves.
//          Each lane: 3 float4 per half-row (64 lanes span the 768-f row).
// ---------------------------------------------------------------------------
__global__ void __launch_bounds__(256) fused_pool_kernel(
    const float* __restrict__ hs,      // [B, S, H]
    const int*   __restrict__ lens,    // [B, T]
    float*       __restrict__ out)     // [B, T, H]
{
    const int b     = blockIdx.x / NCHUNK;
    const int chunk = blockIdx.x % NCHUNK;
    const int t0    = chunk * TOK_PER_CTA;

    const int tid  = threadIdx.x;
    const int lane = tid & 31;
    const int wid  = tid >> 5;

    const int* L = lens + (size_t)b * T;

    __shared__ int wsum[8];
    __shared__ int s_desc[TOK_PER_CTA];   // start | (len << 16)

    // ---- Phase 1a: partial sums of lens[b][0..t0) (t0 <= 1984) ----
    int part = 0;
    for (int i = tid; i < t0; i += 256) part += L[i];
#pragma unroll
    for (int off = 16; off > 0; off >>= 1)
        part += __shfl_down_sync(0xffffffffu, part, off);
    if (lane == 0) wsum[wid] = part;
    __syncthreads();

    // ---- Phase 1b: warp 0 finishes base + scans the chunk's 32 lens ----
    if (wid == 0) {
        int v = (lane < 8) ? wsum[lane] : 0;
        v += __shfl_xor_sync(0xffffffffu, v, 4);
        v += __shfl_xor_sync(0xffffffffu, v, 2);
        v += __shfl_xor_sync(0xffffffffu, v, 1);
        const int base = __shfl_sync(0xffffffffu, v, 0);

        const int tok = t0 + lane;
        const int len = (tok < T) ? L[tok] : 0;
        int incl = len;
#pragma unroll
        for (int off = 1; off < 32; off <<= 1) {
            int n = __shfl_up_sync(0xffffffffu, incl, off);
            if (lane >= off) incl += n;
        }
        s_desc[lane] = (base + incl - len) | (len << 16);
    }
    __syncthreads();

    // ---- Phase 2: 64 half-tokens, warp w takes halves w, w+8, ..., w+56 ----
    const int nhalf = (min(T - t0, TOK_PER_CTA)) * 2;   // 64 (or 32 for last chunk)

    for (int h = wid; h < nhalf; h += 8) {
        const int i    = h >> 1;          // token within chunk
        const int half = h & 1;

        const int desc  = s_desc[i];
        const int start = desc & 0xFFFF;
        const int len   = desc >> 16;

        const int tok   = t0 + i;
        const int f4off = half * 96 + lane;   // 96 float4 per half-row

        float4* dst = (float4*)(out + ((size_t)b * T + tok) * H);

        if (len == 0) {
            const float4 z = make_float4(0.f, 0.f, 0.f, 0.f);
#pragma unroll
            for (int k = 0; k < 3; k++) dst[f4off + 32 * k] = z;
            continue;
        }

        // First covered position is 1 + start (1-based positions)
        const size_t row0 = (size_t)b * S + 1 + start;
        const float4* src0 = (const float4*)(hs + row0 * H);

        float4 acc[3];
#pragma unroll
        for (int k = 0; k < 3; k++) acc[k] = src0[f4off + 32 * k];

        if (len == 2) {
            const float4* src1 = src0 + (H / 4);
#pragma unroll
            for (int k = 0; k < 3; k++) {
                float4 v = src1[f4off + 32 * k];
                acc[k].x = (acc[k].x + v.x) * 0.5f;
                acc[k].y = (acc[k].y + v.y) * 0.5f;
                acc[k].z = (acc[k].z + v.z) * 0.5f;
                acc[k].w = (acc[k].w + v.w) * 0.5f;
            }
        }

#pragma unroll
        for (int k = 0; k < 3; k++) dst[f4off + 32 * k] = acc[k];
    }
}

// ---------------------------------------------------------------------------
extern "C" void kernel_launch(void* const* d_in, const int* in_sizes, int n_in,
                              void* d_out, int out_size)
{
    const float* hs   = (const float*)d_in[0];   // [B,S,H] fp32
    const int*   lens = (const int*)d_in[1];     // [B,T] int32
    float*       out  = (float*)d_out;           // [B,T,H] fp32

    (void)in_sizes; (void)n_in; (void)out_size;

    fused_pool_kernel<<<B * NCHUNK, 256>>>(hs, lens, out);
}

// round 8
// speedup vs baseline: 1.0618x; 1.0618x over previous
#include <cuda_runtime.h>
#include <cuda_bf16.h>
#include <cstdint>

// Problem constants
#define B 16
#define S 4096
#define H 768
#define T 2000

#define GRID   8000            // B*T*2 half-tokens / 8 warps per CTA
#define TPB    256

// Packed per-token descriptor: start | (len << 16). start <= 4000, len in {0,1,2}.
__device__ int g_desc[B * T];
// Per-batch ready flags, padded to separate 128B lines. Zero-initialized; reset
// by the last exiting CTA so every graph replay starts clean.
__device__ int g_ready[B * 32];
__device__ int g_exit;

// ---------------------------------------------------------------------------
// Single launch. CTAs 0..B-1 additionally scan one batch's lengths and publish
// packed descriptors + a ready flag. All CTAs then pool: 8 warps per CTA, one
// half-token (384 floats) per warp; CTA c covers tokens [4c, 4c+4) -> one batch.
// ---------------------------------------------------------------------------
__global__ void __launch_bounds__(TPB) fused_pool_kernel(
    const float* __restrict__ hs,      // [B, S, H]
    const int*   __restrict__ lens,    // [B, T]
    float*       __restrict__ out)     // [B, T, H]
{
    const int cta  = blockIdx.x;
    const int tid  = threadIdx.x;
    const int lane = tid & 31;
    const int wid  = tid >> 5;

    // ==== Scan duty for CTAs 0..B-1 (batch = cta) ====
    if (cta < B) {
        const int* L = lens + (size_t)cta * T;
        const int idx0 = tid * 8;

        int v[8];
        if (idx0 + 8 <= T) {
            int4 a = *(const int4*)(L + idx0);
            int4 c = *(const int4*)(L + idx0 + 4);
            v[0] = a.x; v[1] = a.y; v[2] = a.z; v[3] = a.w;
            v[4] = c.x; v[5] = c.y; v[6] = c.z; v[7] = c.w;
        } else {
#pragma unroll
            for (int i = 0; i < 8; i++) v[i] = (idx0 + i < T) ? L[idx0 + i] : 0;
        }

        int pre[8], s = 0;
#pragma unroll
        for (int i = 0; i < 8; i++) { pre[i] = s; s += v[i]; }

        // warp inclusive scan of thread sums
        int incl = s;
#pragma unroll
        for (int off = 1; off < 32; off <<= 1) {
            int n = __shfl_up_sync(0xffffffffu, incl, off);
            if (lane >= off) incl += n;
        }
        const int excl = incl - s;

        __shared__ int wsums[8];
        if (lane == 31) wsums[wid] = incl;
        __syncthreads();
        if (wid == 0) {
            int w = (lane < 8) ? wsums[lane] : 0;
            int wi = w;
#pragma unroll
            for (int off = 1; off < 8; off <<= 1) {
                int n = __shfl_up_sync(0xffffffffu, wi, off);
                if (lane >= off) wi += n;
            }
            if (lane < 8) wsums[lane] = wi - w;   // exclusive
        }
        __syncthreads();

        const int base = wsums[wid] + excl;
        if (idx0 + 8 <= T) {
            int4 d0, d1;
            d0.x = (base + pre[0]) | (v[0] << 16);
            d0.y = (base + pre[1]) | (v[1] << 16);
            d0.z = (base + pre[2]) | (v[2] << 16);
            d0.w = (base + pre[3]) | (v[3] << 16);
            d1.x = (base + pre[4]) | (v[4] << 16);
            d1.y = (base + pre[5]) | (v[5] << 16);
            d1.z = (base + pre[6]) | (v[6] << 16);
            d1.w = (base + pre[7]) | (v[7] << 16);
            *(int4*)(g_desc + (size_t)cta * T + idx0)     = d0;
            *(int4*)(g_desc + (size_t)cta * T + idx0 + 4) = d1;
        } else {
#pragma unroll
            for (int i = 0; i < 8; i++)
                if (idx0 + i < T)
                    g_desc[(size_t)cta * T + idx0 + i] = (base + pre[i]) | (v[i] << 16);
        }

        __threadfence();
        __syncthreads();
        if (tid == 0) atomicExch(&g_ready[cta * 32], 1);
    }

    // ==== Which batch do this CTA's tokens belong to? (never spans: 2000 % 4 == 0)
    const int b = (cta * 4) / T;

    // ==== Wait for this batch's descriptors ====
    if (tid == 0) {
        while (__ldcg(&g_ready[b * 32]) == 0) __nanosleep(128);
    }
    __syncthreads();

    // ==== Pool: warp wid handles half-token gwarp = cta*8 + wid ====
    {
        const int gwarp = cta * 8 + wid;
        const int tok   = gwarp >> 1;
        const int half  = gwarp & 1;

        const int desc  = __ldcg(g_desc + tok);
        const int start = desc & 0xFFFF;
        const int len   = desc >> 16;

        const int f4off = half * 96 + lane;       // 96 float4 per half-row
        float4* dst = (float4*)(out + (size_t)tok * H);

        if (len == 0) {
            const float4 z = make_float4(0.f, 0.f, 0.f, 0.f);
#pragma unroll
            for (int k = 0; k < 3; k++) dst[f4off + 32 * k] = z;
        } else {
            // First covered position is 1 + start (1-based positions)
            const size_t row0 = (size_t)b * S + 1 + start;
            const float4* src0 = (const float4*)(hs + row0 * H);

            float4 acc[3];
#pragma unroll
            for (int k = 0; k < 3; k++) acc[k] = src0[f4off + 32 * k];

            if (len == 2) {
                const float4* src1 = src0 + (H / 4);
#pragma unroll
                for (int k = 0; k < 3; k++) {
                    float4 v = src1[f4off + 32 * k];
                    acc[k].x = (acc[k].x + v.x) * 0.5f;
                    acc[k].y = (acc[k].y + v.y) * 0.5f;
                    acc[k].z = (acc[k].z + v.z) * 0.5f;
                    acc[k].w = (acc[k].w + v.w) * 0.5f;
                }
            }

#pragma unroll
            for (int k = 0; k < 3; k++) dst[f4off + 32 * k] = acc[k];
        }
    }

    // ==== Exit protocol: last CTA resets flags for the next graph replay ====
    __syncthreads();
    if (tid == 0) {
        __threadfence();
        const int old = atomicAdd(&g_exit, 1);
        if (old == GRID - 1) {
            g_exit = 0;
#pragma unroll
            for (int i = 0; i < B; i++) g_ready[i * 32] = 0;
            __threadfence();
        }
    }
}

// ---------------------------------------------------------------------------
extern "C" void kernel_launch(void* const* d_in, const int* in_sizes, int n_in,
                              void* d_out, int out_size)
{
    const float* hs   = (const float*)d_in[0];   // [B,S,H] fp32
    const int*   lens = (const int*)d_in[1];     // [B,T] int32
    float*       out  = (float*)d_out;           // [B,T,H] fp32

    (void)in_sizes; (void)n_in; (void)out_size;

    fused_pool_kernel<<<GRID, TPB>>>(hs, lens, out);
}

// round 9
// speedup vs baseline: 1.1036x; 1.0394x over previous
#include <cuda_runtime.h>
#include <cuda_bf16.h>
#include <cstdint>

// Problem constants
#define B 16
#define S 4096
#define H 768
#define T 2000

// Packed per-token descriptor: start | (len << 16). start <= 4000, len in {0,1,2}.
__device__ int g_desc[B * T];

// ---------------------------------------------------------------------------
// Kernel 1: per-batch exclusive prefix sum over T lengths (shuffle scan),
// writing packed (start, len) descriptors. Fires PDL trigger when done.
// ---------------------------------------------------------------------------
__global__ void __launch_bounds__(1024) scan_kernel(const int* __restrict__ lens) {
    const int b    = blockIdx.x;
    const int tid  = threadIdx.x;
    const int lane = tid & 31;
    const int wid  = tid >> 5;

    const int* L = lens + (size_t)b * T;

    const int idx0 = tid * 2;
    int v0 = 0, v1 = 0;
    if (idx0 + 1 < T) {
        int2 v = *(const int2*)(L + idx0);
        v0 = v.x; v1 = v.y;
    } else if (idx0 < T) {
        v0 = L[idx0];
    }
    int tsum = v0 + v1;

    int incl = tsum;
#pragma unroll
    for (int off = 1; off < 32; off <<= 1) {
        int n = __shfl_up_sync(0xffffffffu, incl, off);
        if (lane >= off) incl += n;
    }
    const int excl = incl - tsum;

    __shared__ int warpsums[32];
    if (lane == 31) warpsums[wid] = incl;
    __syncthreads();

    if (wid == 0) {
        int w = warpsums[lane];
        int wi = w;
#pragma unroll
        for (int off = 1; off < 32; off <<= 1) {
            int n = __shfl_up_sync(0xffffffffu, wi, off);
            if (lane >= off) wi += n;
        }
        warpsums[lane] = wi - w;
    }
    __syncthreads();

    const int base = warpsums[wid] + excl;
    if (idx0 + 1 < T) {
        int2 d;
        d.x = base | (v0 << 16);
        d.y = (base + v0) | (v1 << 16);
        *(int2*)(g_desc + (size_t)b * T + idx0) = d;
    } else if (idx0 < T) {
        g_desc[(size_t)b * T + idx0] = base | (v0 << 16);
    }

    // All descriptor writes issued; make them visible and allow the pool
    // kernel's grid to launch (PDL trigger).
    __threadfence();
    asm volatile("griddepcontrol.launch_dependents;" ::: "memory");
}

// ---------------------------------------------------------------------------
// Kernel 2: HALF a token per warp. Each lane handles 3 float4 (48B);
// 64 lanes (2 warps) cover the 768-float row. One index load per warp.
// Opens with PDL wait so its launch/rollout overlaps the scan.
// ---------------------------------------------------------------------------
__global__ void __launch_bounds__(256) pool_kernel(
    const float* __restrict__ hs,      // [B, S, H]
    float*       __restrict__ out)     // [B, T, H]
{
    // Wait until the scan grid's writes are visible (PDL).
    asm volatile("griddepcontrol.wait;" ::: "memory");

    const int gwarp = (blockIdx.x * blockDim.x + threadIdx.x) >> 5;
    const int lane  = threadIdx.x & 31;
    const int tok   = gwarp >> 1;            // token index
    const int half  = gwarp & 1;             // which half of the row
    if (tok >= B * T) return;

    const int desc  = __ldg(g_desc + tok);
    const int start = desc & 0xFFFF;
    const int len   = desc >> 16;
    const int b     = tok / T;

    const int f4off = half * 96 + lane;      // 96 float4 per half-row

    float4* dst = (float4*)(out + (size_t)tok * H);

    if (len == 0) {
        const float4 z = make_float4(0.f, 0.f, 0.f, 0.f);
#pragma unroll
        for (int k = 0; k < 3; k++) dst[f4off + 32 * k] = z;
        return;
    }

    // First covered position is 1 + start (1-based positions)
    const size_t row0 = (size_t)b * S + 1 + start;
    const float4* src0 = (const float4*)(hs + row0 * H);

    float4 acc[3];
#pragma unroll
    for (int k = 0; k < 3; k++) acc[k] = src0[f4off + 32 * k];

    if (len == 2) {
        const float4* src1 = src0 + (H / 4);
#pragma unroll
        for (int k = 0; k < 3; k++) {
            float4 v = src1[f4off + 32 * k];
            acc[k].x = (acc[k].x + v.x) * 0.5f;
            acc[k].y = (acc[k].y + v.y) * 0.5f;
            acc[k].z = (acc[k].z + v.z) * 0.5f;
            acc[k].w = (acc[k].w + v.w) * 0.5f;
        }
    }

#pragma unroll
    for (int k = 0; k < 3; k++) dst[f4off + 32 * k] = acc[k];
}

// ---------------------------------------------------------------------------
extern "C" void kernel_launch(void* const* d_in, const int* in_sizes, int n_in,
                              void* d_out, int out_size)
{
    const float* hs   = (const float*)d_in[0];   // [B,S,H] fp32
    const int*   lens = (const int*)d_in[1];     // [B,T] int32
    float*       out  = (float*)d_out;           // [B,T,H] fp32

    (void)in_sizes; (void)n_in; (void)out_size;

    scan_kernel<<<B, 1024>>>(lens);

    // Pool launch with Programmatic Dependent Launch: overlap launch/rollout
    // with the scan kernel's execution.
    const int n_warps = B * T * 2;               // 64000 half-token warps
    const int blocks  = n_warps / 8;             // 8000 CTAs of 256 threads

    cudaLaunchConfig_t cfg = {};
    cfg.gridDim  = dim3(blocks, 1, 1);
    cfg.blockDim = dim3(256, 1, 1);
    cfg.dynamicSmemBytes = 0;
    cfg.stream = (cudaStream_t)0;  // legacy default stream (same as <<<>>>)

    cudaLaunchAttribute attrs[1];
    attrs[0].id = cudaLaunchAttributeProgrammaticStreamSerialization;
    attrs[0].val.programmaticStreamSerializationAllowed = 1;
    cfg.attrs = attrs;
    cfg.numAttrs = 1;

    cudaError_t err = cudaLaunchKernelEx(&cfg, pool_kernel, hs, out);
    if (err != cudaSuccess) {
        // Fallback: plain launch (griddepcontrol.wait is a no-op without PDL).
        pool_kernel<<<blocks, 256>>>(hs, out);
    }
}